// round 3
// baseline (speedup 1.0000x reference)
#include <cuda_runtime.h>
#include <math.h>

#define ZTOT  65536
#define KTOT  204
#define NPATH 60
#define NOUT  324
#define ZT    32
#define NT    64

// scratch: F[k][z]  (53.5 MB static device array — allowed scratch path)
__device__ float g_F[(size_t)KTOT * ZTOT];

__device__ __forceinline__ unsigned long long ffma2(unsigned long long a,
                                                    unsigned long long b,
                                                    unsigned long long c) {
  unsigned long long d;
  asm("fma.rn.f32x2 %0, %1, %2, %3;" : "=l"(d) : "l"(a), "l"(b), "l"(c));
  return d;
}

// ---------------------------------------------------------------------------
// Kernel 1: per-point radial MLP + spherical harmonics -> F[k][z]
// one thread per z; W1/W2 in shared (warp-broadcast LDS), H staged in shared.
// ---------------------------------------------------------------------------
__global__ __launch_bounds__(128) void feat_kernel(
    const float* __restrict__ r,  const float* __restrict__ W1,
    const float* __restrict__ b1, const float* __restrict__ W2,
    const float* __restrict__ b2) {
  extern __shared__ float sm[];
  float* sW1 = sm;                 // 4096
  float* sW2 = sm + 4096;          // 3840
  float* sb1 = sW2 + 3840;         // 64
  float* sb2 = sb1 + 64;           // 64 (60 used)
  float* sH  = sb2 + 64;           // 128*64
  const int tid = threadIdx.x;

  #pragma unroll
  for (int i = 0; i < 32; ++i) sW1[tid + i*128] = W1[tid + i*128];
  #pragma unroll
  for (int i = 0; i < 30; ++i) sW2[tid + i*128] = W2[tid + i*128];
  if (tid < 64) sb1[tid] = b1[tid];
  if (tid < 60) sb2[tid] = b2[tid];
  __syncthreads();

  const int z = blockIdx.x * 128 + tid;
  const float rx = r[3*z+0], ry = r[3*z+1], rz = r[3*z+2];
  const float rad = sqrtf(rx*rx + ry*ry + rz*rz);
  const float inv = 1.0f / (rad + 1e-12f);
  const float x = rx*inv, y = ry*inv, zc = rz*inv;

  float Y[9];
  Y[0] = 0.28209479177387814f;
  Y[1] = 0.4886025119029199f * y;
  Y[2] = 0.4886025119029199f * zc;
  Y[3] = 0.4886025119029199f * x;
  Y[4] = 1.0925484305920792f * x * y;
  Y[5] = 1.0925484305920792f * y * zc;
  Y[6] = 0.31539156525252005f * (3.0f*zc*zc - 1.0f);
  Y[7] = 1.0925484305920792f * x * zc;
  Y[8] = 0.5462742152960396f * (x*x - y*y);

  // radial basis (centers = linspace(0, 3.5, 64))
  float B[64];
  #pragma unroll
  for (int j = 0; j < 64; ++j) {
    float d = rad - (3.5f/63.0f) * (float)j;
    B[j] = expf(-4.0f * d * d);
  }

  // hidden = relu(B @ W1 + b1) -> shared (dynamic h index)
  for (int h = 0; h < 64; ++h) {
    float a = sb1[h];
    #pragma unroll
    for (int j = 0; j < 64; ++j) a = fmaf(B[j], sW1[j*64 + h], a);
    sH[h*128 + tid] = fmaxf(a, 0.0f);
  }

  // R = H @ W2 + b2  (R stays in registers; p-loop fully unrolled)
  float R[NPATH];
  #pragma unroll
  for (int p = 0; p < NPATH; ++p) R[p] = sb2[p];
  for (int h = 0; h < 64; ++h) {
    float hv = sH[h*128 + tid];
    #pragma unroll
    for (int p = 0; p < NPATH; ++p) R[p] = fmaf(hv, sW2[h*60 + p], R[p]);
  }

  // F[k] = R[path(k)] * Y[yidx(k)]  — coalesced STG across z.
  // path tables derived from reference _filter_paths():
  // lf per (l_in,l_out) block (each x4 for MUL*MUL), k-offset per block.
  constexpr int LF[15]   = {0,1,2,1,0,1,2,1,2,2,1,2,0,1,2};
  constexpr int GOFF[15] = {0,4,16,36,48,52,64,84,96,116,136,148,168,172,184};
  #pragma unroll
  for (int p = 0; p < NPATH; ++p) {
    const int l  = LF[p >> 2];
    const int yo = (l == 0) ? 0 : ((l == 1) ? 1 : 4);
    const int kb = GOFF[p >> 2] + (p & 3) * (2*l + 1);
    #pragma unroll
    for (int m = 0; m < 2*l + 1; ++m)
      g_F[(size_t)(kb + m) * ZTOT + z] = R[p] * Y[yo + m];
  }
}

// ---------------------------------------------------------------------------
// Kernel 2: out[Z,324] = F[Z,204] @ cg[204,324]
// block tile 32z x 64col; F stored DUPLICATED ((f,f) pairs) in shared so the
// inner loop is 2x LDS.128 + 4x fma.rn.f32x2 per thread per k (8 MACs).
// ---------------------------------------------------------------------------
__global__ __launch_bounds__(256) void contract_kernel(
    const float* __restrict__ cg, float* __restrict__ out) {
  extern __shared__ float sm[];
  float* Fs = sm;               // KTOT * 64 floats (32 z, duplicated)
  float* Cs = sm + KTOT * 64;   // KTOT * 64 floats
  const int tid = threadIdx.x;
  const int zb = blockIdx.y * ZT;
  const int jb = blockIdx.x * NT;

  { // F tile, duplicated pairs
    const float4* gF4 = (const float4*)g_F;
    float4* Fs4 = (float4*)Fs;
    for (int i = tid; i < KTOT * 8; i += 256) {
      int k = i >> 3, q = i & 7;
      float4 v = gF4[(size_t)k * (ZTOT/4) + (zb >> 2) + q];
      Fs4[k*16 + q*2 + 0] = make_float4(v.x, v.x, v.y, v.y);
      Fs4[k*16 + q*2 + 1] = make_float4(v.z, v.z, v.w, v.w);
    }
  }
  { // cg tile (zero-pad cols >= 324)
    const float4* cg4 = (const float4*)cg;
    float4* Cs4 = (float4*)Cs;
    for (int i = tid; i < KTOT * 16; i += 256) {
      int k = i >> 4, q = i & 15;
      int col = jb + q*4;
      Cs4[k*16 + q] = (col < NOUT) ? cg4[k*(NOUT/4) + (jb >> 2) + q]
                                   : make_float4(0.f, 0.f, 0.f, 0.f);
    }
  }
  __syncthreads();

  const int ty = tid >> 4;   // z pair index  (zz = 2*ty, 2*ty+1)
  const int tx = tid & 15;   // 4-col group
  const ulonglong2* F2 = (const ulonglong2*)Fs;
  const ulonglong2* C2 = (const ulonglong2*)Cs;

  unsigned long long a00 = 0ull, a01 = 0ull, a10 = 0ull, a11 = 0ull;
  #pragma unroll 4
  for (int k = 0; k < KTOT; ++k) {
    ulonglong2 f = F2[k*16 + ty];  // (F[z0],F[z0]) , (F[z1],F[z1])
    ulonglong2 c = C2[k*16 + tx];  // (c0,c1) , (c2,c3)
    a00 = ffma2(f.x, c.x, a00);
    a01 = ffma2(f.x, c.y, a01);
    a10 = ffma2(f.y, c.x, a10);
    a11 = ffma2(f.y, c.y, a11);
  }

  const int col = jb + tx*4;
  if (col < NOUT) {
    union Cvt { unsigned long long u; float2 f; };
    Cvt u00, u01, u10, u11;
    u00.u = a00; u01.u = a01; u10.u = a10; u11.u = a11;
    const int z0 = zb + ty*2;
    *(float4*)&out[(size_t)z0       * NOUT + col] =
        make_float4(u00.f.x, u00.f.y, u01.f.x, u01.f.y);
    *(float4*)&out[(size_t)(z0 + 1) * NOUT + col] =
        make_float4(u10.f.x, u10.f.y, u11.f.x, u11.f.y);
  }
}

// ---------------------------------------------------------------------------
extern "C" void kernel_launch(void* const* d_in, const int* in_sizes, int n_in,
                              void* d_out, int out_size) {
  const float* r  = (const float*)d_in[0];
  const float* W1 = (const float*)d_in[1];
  const float* b1 = (const float*)d_in[2];
  const float* W2 = (const float*)d_in[3];
  const float* b2 = (const float*)d_in[4];
  const float* cg = (const float*)d_in[5];
  float* out = (float*)d_out;

  const int smem1 = (4096 + 3840 + 64 + 64 + 128*64) * 4;   // 65024 B
  const int smem2 = 2 * KTOT * 64 * 4;                      // 104448 B
  cudaFuncSetAttribute(feat_kernel,
      cudaFuncAttributeMaxDynamicSharedMemorySize, smem1);
  cudaFuncSetAttribute(contract_kernel,
      cudaFuncAttributeMaxDynamicSharedMemorySize, smem2);

  feat_kernel<<<ZTOT/128, 128, smem1>>>(r, W1, b1, W2, b2);
  contract_kernel<<<dim3((NOUT + NT - 1)/NT, ZTOT/ZT), 256, smem2>>>(cg, out);
}

// round 5
// speedup vs baseline: 1.2538x; 1.2538x over previous
#include <cuda_runtime.h>
#include <math.h>

#define ZTOT  65536
#define KTOT  204
#define NPATH 60
#define NOUT  324

// contract tiling
#define BZ    256      // z per block
#define BC    128      // cols per block
#define KC    12       // k per chunk (204 = 17 * 12)
#define NCH   17
#define TZ    16       // z per thread
#define TC    8        // cols per thread

// scratch: F[k][z]  (53.5 MB static device array — allowed scratch path)
__device__ float g_F[(size_t)KTOT * ZTOT];

__device__ __forceinline__ unsigned long long ffma2(unsigned long long a,
                                                    unsigned long long b,
                                                    unsigned long long c) {
  unsigned long long d;
  asm("fma.rn.f32x2 %0, %1, %2, %3;" : "=l"(d) : "l"(a), "l"(b), "l"(c));
  return d;
}

// ---------------------------------------------------------------------------
// Kernel 1: per-point radial MLP + spherical harmonics -> F[k][z]
// ---------------------------------------------------------------------------
__global__ __launch_bounds__(128) void feat_kernel(
    const float* __restrict__ r,  const float* __restrict__ W1,
    const float* __restrict__ b1, const float* __restrict__ W2,
    const float* __restrict__ b2) {
  extern __shared__ float sm[];
  float* sW1 = sm;                 // 4096
  float* sW2 = sm + 4096;          // 3840
  float* sb1 = sW2 + 3840;         // 64
  float* sb2 = sb1 + 64;           // 64 (60 used)
  float* sH  = sb2 + 64;           // 128*64
  const int tid = threadIdx.x;

  #pragma unroll
  for (int i = 0; i < 32; ++i) sW1[tid + i*128] = W1[tid + i*128];
  #pragma unroll
  for (int i = 0; i < 30; ++i) sW2[tid + i*128] = W2[tid + i*128];
  if (tid < 64) sb1[tid] = b1[tid];
  if (tid < 60) sb2[tid] = b2[tid];
  __syncthreads();

  const int z = blockIdx.x * 128 + tid;
  const float rx = r[3*z+0], ry = r[3*z+1], rz = r[3*z+2];
  const float rad = sqrtf(rx*rx + ry*ry + rz*rz);
  const float inv = 1.0f / (rad + 1e-12f);
  const float x = rx*inv, y = ry*inv, zc = rz*inv;

  float Y[9];
  Y[0] = 0.28209479177387814f;
  Y[1] = 0.4886025119029199f * y;
  Y[2] = 0.4886025119029199f * zc;
  Y[3] = 0.4886025119029199f * x;
  Y[4] = 1.0925484305920792f * x * y;
  Y[5] = 1.0925484305920792f * y * zc;
  Y[6] = 0.31539156525252005f * (3.0f*zc*zc - 1.0f);
  Y[7] = 1.0925484305920792f * x * zc;
  Y[8] = 0.5462742152960396f * (x*x - y*y);

  float B[64];
  #pragma unroll
  for (int j = 0; j < 64; ++j) {
    float d = rad - (3.5f/63.0f) * (float)j;
    B[j] = expf(-4.0f * d * d);
  }

  for (int h = 0; h < 64; ++h) {
    float a = sb1[h];
    #pragma unroll
    for (int j = 0; j < 64; ++j) a = fmaf(B[j], sW1[j*64 + h], a);
    sH[h*128 + tid] = fmaxf(a, 0.0f);
  }

  float R[NPATH];
  #pragma unroll
  for (int p = 0; p < NPATH; ++p) R[p] = sb2[p];
  for (int h = 0; h < 64; ++h) {
    float hv = sH[h*128 + tid];
    #pragma unroll
    for (int p = 0; p < NPATH; ++p) R[p] = fmaf(hv, sW2[h*60 + p], R[p]);
  }

  constexpr int LF[15]   = {0,1,2,1,0,1,2,1,2,2,1,2,0,1,2};
  constexpr int GOFF[15] = {0,4,16,36,48,52,64,84,96,116,136,148,168,172,184};
  #pragma unroll
  for (int p = 0; p < NPATH; ++p) {
    const int l  = LF[p >> 2];
    const int yo = (l == 0) ? 0 : ((l == 1) ? 1 : 4);
    const int kb = GOFF[p >> 2] + (p & 3) * (2*l + 1);
    #pragma unroll
    for (int m = 0; m < 2*l + 1; ++m)
      g_F[(size_t)(kb + m) * ZTOT + z] = R[p] * Y[yo + m];
  }
}

// ---------------------------------------------------------------------------
// Kernel 2: out[Z,324] = F[Z,204] @ cg[204,324]
// Block tile 256z x 128c, thread tile 16z x 8c.
// F: natural adjacent z-pairs go into f32x2 lanes (no duplication needed).
// cg: duplicated (c,c) u64 at staging. Inner loop per k:
//   4x LDS.128 (F) + 4x LDS.128 (Cdup) + 64x fma.rn.f32x2  = 128 MACs / 128 B.
// Double-buffered k-chunks of 12 (204 = 17*12).
// ---------------------------------------------------------------------------
__global__ __launch_bounds__(256, 1) void contract_kernel(
    const float* __restrict__ cg, float* __restrict__ out) {
  extern __shared__ char smraw[];
  // layout: Cdup[2][KC*BC] u64, then Fs[2][KC*BZ] float
  unsigned long long* Cd = (unsigned long long*)smraw;          // 2*1536 u64
  float* Fs = (float*)(smraw + 2 * KC * BC * 8);                // 2*3072 f32

  const int tid = threadIdx.x;
  const int tc  = tid & 15;        // 16 col-threads * 8 cols = 128
  const int tz  = tid >> 4;        // 16 z-threads  * 16 z   = 256
  const int zb  = blockIdx.y * BZ;
  const int jb  = blockIdx.x * BC;

  const float4* gF4 = (const float4*)g_F;

  auto load_chunk = [&](int k0, int buf) {
    // F: KC*BZ floats = 768 float4
    float4* Fd4 = (float4*)(Fs + buf * (KC * BZ));
    #pragma unroll
    for (int it = 0; it < 3; ++it) {
      int i = tid + it * 256;            // 0..767
      int k = i >> 6, zi = i & 63;
      Fd4[i] = gF4[(size_t)(k0 + k) * (ZTOT/4) + (zb >> 2) + zi];
    }
    // C: KC*BC = 1536 duplicated u64
    unsigned long long* Cb = Cd + buf * (KC * BC);
    #pragma unroll
    for (int it = 0; it < 6; ++it) {
      int i = tid + it * 256;            // 0..1535
      int k = i >> 7, c = i & 127;
      int col = jb + c;
      float v = (col < NOUT) ? cg[(k0 + k) * NOUT + col] : 0.0f;
      union { float2 f; unsigned long long u; } d;
      d.f.x = v; d.f.y = v;
      Cb[i] = d.u;
    }
  };

  unsigned long long acc[TZ/2][TC];
  #pragma unroll
  for (int p = 0; p < TZ/2; ++p)
    #pragma unroll
    for (int c = 0; c < TC; ++c) acc[p][c] = 0ull;

  load_chunk(0, 0);
  __syncthreads();

  for (int ch = 0; ch < NCH; ++ch) {
    const int cur = ch & 1;
    if (ch + 1 < NCH) load_chunk((ch + 1) * KC, cur ^ 1);

    const ulonglong2* Fp = (const ulonglong2*)(Fs + cur * (KC * BZ) + tz * TZ);
    const ulonglong2* Cp = (const ulonglong2*)(Cd + cur * (KC * BC) + tc * TC);

    #pragma unroll 2
    for (int kk = 0; kk < KC; ++kk) {
      unsigned long long f[TZ/2], c[TC];
      #pragma unroll
      for (int q = 0; q < TZ/4; ++q) {           // 4x LDS.128
        // one k-row of F = BZ floats = BZ/4 ulonglong2
        ulonglong2 v = Fp[(size_t)kk * (BZ/4) + q];
        f[2*q] = v.x; f[2*q+1] = v.y;
      }
      #pragma unroll
      for (int q = 0; q < TC/2; ++q) {           // 4x LDS.128
        // one k-row of Cdup = BC u64 = BC/2 ulonglong2
        ulonglong2 v = Cp[(size_t)kk * (BC/2) + q];
        c[2*q] = v.x; c[2*q+1] = v.y;
      }
      #pragma unroll
      for (int p = 0; p < TZ/2; ++p)
        #pragma unroll
        for (int cc = 0; cc < TC; ++cc)
          acc[p][cc] = ffma2(f[p], c[cc], acc[p][cc]);
    }
    __syncthreads();
  }

  // epilogue: acc[p][c] = (out[z0+2p, col], out[z0+2p+1, col])
  const int col0 = jb + tc * TC;
  union Cvt { unsigned long long u; float2 f; };
  #pragma unroll
  for (int p = 0; p < TZ/2; ++p) {
    const int z0 = zb + tz * TZ + 2 * p;
    Cvt v[TC];
    #pragma unroll
    for (int cc = 0; cc < TC; ++cc) v[cc].u = acc[p][cc];
    if (col0 < NOUT)
      *(float4*)&out[(size_t)z0 * NOUT + col0] =
          make_float4(v[0].f.x, v[1].f.x, v[2].f.x, v[3].f.x);
    if (col0 + 4 < NOUT)
      *(float4*)&out[(size_t)z0 * NOUT + col0 + 4] =
          make_float4(v[4].f.x, v[5].f.x, v[6].f.x, v[7].f.x);
    if (col0 < NOUT)
      *(float4*)&out[(size_t)(z0 + 1) * NOUT + col0] =
          make_float4(v[0].f.y, v[1].f.y, v[2].f.y, v[3].f.y);
    if (col0 + 4 < NOUT)
      *(float4*)&out[(size_t)(z0 + 1) * NOUT + col0 + 4] =
          make_float4(v[4].f.y, v[5].f.y, v[6].f.y, v[7].f.y);
  }
}

// ---------------------------------------------------------------------------
extern "C" void kernel_launch(void* const* d_in, const int* in_sizes, int n_in,
                              void* d_out, int out_size) {
  const float* r  = (const float*)d_in[0];
  const float* W1 = (const float*)d_in[1];
  const float* b1 = (const float*)d_in[2];
  const float* W2 = (const float*)d_in[3];
  const float* b2 = (const float*)d_in[4];
  const float* cg = (const float*)d_in[5];
  float* out = (float*)d_out;

  const int smem1 = (4096 + 3840 + 64 + 64 + 128*64) * 4;        // 65024 B
  const int smem2 = 2 * KC * BC * 8 + 2 * KC * BZ * 4;           // 49152 B
  cudaFuncSetAttribute(feat_kernel,
      cudaFuncAttributeMaxDynamicSharedMemorySize, smem1);
  cudaFuncSetAttribute(contract_kernel,
      cudaFuncAttributeMaxDynamicSharedMemorySize, smem2);

  feat_kernel<<<ZTOT/128, 128, smem1>>>(r, W1, b1, W2, b2);
  contract_kernel<<<dim3((NOUT + BC - 1)/BC, ZTOT/BZ), 256, smem2>>>(cg, out);
}

// round 7
// speedup vs baseline: 2.5351x; 2.0220x over previous
#include <cuda_runtime.h>
#include <cuda_bf16.h>
#include <math.h>
#include <stdint.h>

#define ZTOT  65536
#define KTOT  204
#define NPATH 60
#define NOUT  324
#define KSEG  224            // per-segment padded K (7 chunks of 32)
#define NCH   21             // 3 segments * 7 chunks
#define NBP   384            // padded B rows

// ---------------- scratch (static device arrays) ----------------
__device__ float g_F[(size_t)KTOT * ZTOT];            // [k][z] fp32
__device__ uint4 g_Fhi4[(size_t)ZTOT * 32];           // [z][256] bf16 hi plane
__device__ uint4 g_Flo4[(size_t)ZTOT * 32];           // [z][256] bf16 lo plane
__device__ __align__(16) __nv_bfloat16 g_B[NBP * 3 * KSEG];  // [n][672] packed segs

// ---------------- helpers ----------------
__device__ __forceinline__ uint32_t smem_u32(const void* p) {
  uint32_t a;
  asm("{ .reg .u64 t; cvta.to.shared.u64 t, %1; cvt.u32.u64 %0, t; }"
      : "=r"(a) : "l"(p));
  return a;
}
__device__ __forceinline__ void cp16(uint32_t smaddr, const void* gptr) {
  asm volatile("cp.async.cg.shared.global [%0], [%1], 16;"
               :: "r"(smaddr), "l"(gptr) : "memory");
}
__device__ __forceinline__ void ldm_x4(uint32_t* r, uint32_t addr) {
  asm volatile("ldmatrix.sync.aligned.m8n8.x4.shared.b16 {%0,%1,%2,%3}, [%4];"
               : "=r"(r[0]), "=r"(r[1]), "=r"(r[2]), "=r"(r[3]) : "r"(addr));
}
__device__ __forceinline__ void mma16816(float* d, const uint32_t* a,
                                         const uint32_t* b) {
  asm volatile(
      "mma.sync.aligned.m16n8k16.row.col.f32.bf16.bf16.f32 "
      "{%0,%1,%2,%3}, {%4,%5,%6,%7}, {%8,%9}, {%0,%1,%2,%3};"
      : "+f"(d[0]), "+f"(d[1]), "+f"(d[2]), "+f"(d[3])
      : "r"(a[0]), "r"(a[1]), "r"(a[2]), "r"(a[3]), "r"(b[0]), "r"(b[1]));
}

// ---------------------------------------------------------------------------
// Kernel 1: per-point radial MLP + spherical harmonics -> F[k][z]
// ---------------------------------------------------------------------------
__global__ __launch_bounds__(128) void feat_kernel(
    const float* __restrict__ r,  const float* __restrict__ W1,
    const float* __restrict__ b1, const float* __restrict__ W2,
    const float* __restrict__ b2) {
  extern __shared__ float sm[];
  float* sW1 = sm;
  float* sW2 = sm + 4096;
  float* sb1 = sW2 + 3840;
  float* sb2 = sb1 + 64;
  float* sH  = sb2 + 64;
  const int tid = threadIdx.x;

  #pragma unroll
  for (int i = 0; i < 32; ++i) sW1[tid + i*128] = W1[tid + i*128];
  #pragma unroll
  for (int i = 0; i < 30; ++i) sW2[tid + i*128] = W2[tid + i*128];
  if (tid < 64) sb1[tid] = b1[tid];
  if (tid < 60) sb2[tid] = b2[tid];
  __syncthreads();

  const int z = blockIdx.x * 128 + tid;
  const float rx = r[3*z+0], ry = r[3*z+1], rz = r[3*z+2];
  const float rad = sqrtf(rx*rx + ry*ry + rz*rz);
  const float inv = 1.0f / (rad + 1e-12f);
  const float x = rx*inv, y = ry*inv, zc = rz*inv;

  float Y[9];
  Y[0] = 0.28209479177387814f;
  Y[1] = 0.4886025119029199f * y;
  Y[2] = 0.4886025119029199f * zc;
  Y[3] = 0.4886025119029199f * x;
  Y[4] = 1.0925484305920792f * x * y;
  Y[5] = 1.0925484305920792f * y * zc;
  Y[6] = 0.31539156525252005f * (3.0f*zc*zc - 1.0f);
  Y[7] = 1.0925484305920792f * x * zc;
  Y[8] = 0.5462742152960396f * (x*x - y*y);

  float B[64];
  #pragma unroll
  for (int j = 0; j < 64; ++j) {
    float d = rad - (3.5f/63.0f) * (float)j;
    B[j] = expf(-4.0f * d * d);
  }

  for (int h = 0; h < 64; ++h) {
    float a = sb1[h];
    #pragma unroll
    for (int j = 0; j < 64; ++j) a = fmaf(B[j], sW1[j*64 + h], a);
    sH[h*128 + tid] = fmaxf(a, 0.0f);
  }

  float R[NPATH];
  #pragma unroll
  for (int p = 0; p < NPATH; ++p) R[p] = sb2[p];
  for (int h = 0; h < 64; ++h) {
    float hv = sH[h*128 + tid];
    #pragma unroll
    for (int p = 0; p < NPATH; ++p) R[p] = fmaf(hv, sW2[h*60 + p], R[p]);
  }

  constexpr int LF[15]   = {0,1,2,1,0,1,2,1,2,2,1,2,0,1,2};
  constexpr int GOFF[15] = {0,4,16,36,48,52,64,84,96,116,136,148,168,172,184};
  #pragma unroll
  for (int p = 0; p < NPATH; ++p) {
    const int l  = LF[p >> 2];
    const int yo = (l == 0) ? 0 : ((l == 1) ? 1 : 4);
    const int kb = GOFF[p >> 2] + (p & 3) * (2*l + 1);
    #pragma unroll
    for (int m = 0; m < 2*l + 1; ++m)
      g_F[(size_t)(kb + m) * ZTOT + z] = R[p] * Y[yo + m];
  }
}

// ---------------------------------------------------------------------------
// Kernel 2: transpose + bf16 split  g_F[k][z] -> g_Fhi4/g_Flo4 [z][256]
// ---------------------------------------------------------------------------
__global__ __launch_bounds__(256) void transpose_kernel() {
  extern __shared__ __nv_bfloat16 smb[];
  __nv_bfloat16* sHi = smb;               // [64][258]
  __nv_bfloat16* sLo = smb + 64 * 258;
  const int tid = threadIdx.x;
  const int zb  = blockIdx.x * 64;
  const int zi  = tid & 63;
  const int kq  = tid >> 6;

  #pragma unroll 4
  for (int it = 0; it < 64; ++it) {
    int k = kq * 64 + it;
    float f = (k < KTOT) ? g_F[(size_t)k * ZTOT + zb + zi] : 0.0f;
    __nv_bfloat16 hi = __float2bfloat16(f);
    __nv_bfloat16 lo = __float2bfloat16(f - __bfloat162float(hi));
    sHi[zi * 258 + k] = hi;
    sLo[zi * 258 + k] = lo;
  }
  __syncthreads();

  const uint32_t* sHi32 = (const uint32_t*)sHi;
  const uint32_t* sLo32 = (const uint32_t*)sLo;
  #pragma unroll
  for (int it = 0; it < 16; ++it) {
    int s = tid + it * 256;
    int plane = s >> 11;
    int row = (s >> 5) & 63;
    int sg  = s & 31;
    const uint32_t* src = plane ? sLo32 : sHi32;
    uint4 v;
    v.x = src[row*129 + sg*4 + 0];
    v.y = src[row*129 + sg*4 + 1];
    v.z = src[row*129 + sg*4 + 2];
    v.w = src[row*129 + sg*4 + 3];
    (plane ? g_Flo4 : g_Fhi4)[(size_t)(zb + row) * 32 + sg] = v;
  }
}

// ---------------------------------------------------------------------------
// Kernel 3: pack B = cg^T with segments {hi, lo, hi} along K' (672)
// ---------------------------------------------------------------------------
__global__ void prepB_kernel(const float* __restrict__ cg) {
  const int n = blockIdx.x;               // 0..383
  for (int kp = threadIdx.x; kp < 3 * KSEG; kp += blockDim.x) {
    const int seg = kp / KSEG;
    const int k = kp - seg * KSEG;
    float v = (n < NOUT && k < KTOT) ? cg[k * NOUT + n] : 0.0f;
    __nv_bfloat16 hi = __float2bfloat16(v);
    __nv_bfloat16 lo = __float2bfloat16(v - __bfloat162float(hi));
    g_B[n * (3 * KSEG) + kp] = (seg == 1) ? lo : hi;
  }
}

// ---------------------------------------------------------------------------
// Kernel 4: mma.sync bf16 GEMM  out[128z x 128c] per CTA, K'=672
// A segments: {hi, hi, lo} planes; B prepacked {hi, lo, hi}.
// smem rows stride 80B (conflict-free ldmatrix); cp.async double buffer.
// ---------------------------------------------------------------------------
#define ABUF 10240
#define BBUF 10240
__global__ __launch_bounds__(256) void mma_kernel(float* __restrict__ out) {
  __shared__ __align__(16) char smem[2 * (ABUF + BBUF)];
  const uint32_t sb = smem_u32(smem);
  const int tid = threadIdx.x;
  const int w = tid >> 5, lane = tid & 31;
  const int wm = w >> 1, wn = w & 1;           // 4 x 2 warp grid
  const int jb = blockIdx.x * 128;
  const int zb = blockIdx.y * 128;

  auto issue = [&](int c, int buf) {
    const int seg = (c >= 14) ? 2 : (c >= 7 ? 1 : 0);
    const int wc  = c - seg * 7;
    const uint4* Asrc = (seg == 2) ? g_Flo4 : g_Fhi4;
    const uint4* Bsrc = (const uint4*)g_B;
    const uint32_t base = sb + buf * (ABUF + BBUF);
    #pragma unroll
    for (int it = 0; it < 2; ++it) {
      int i = tid + it * 256;                  // 0..511
      int row = i >> 2, quad = i & 3;
      cp16(base + row * 80 + quad * 16,
           &Asrc[(size_t)(zb + row) * 32 + wc * 4 + quad]);
      cp16(base + ABUF + row * 80 + quad * 16,
           &Bsrc[(size_t)(jb + row) * 84 + c * 4 + quad]);
    }
    asm volatile("cp.async.commit_group;" ::: "memory");
  };

  float acc[2][8][4];
  #pragma unroll
  for (int mt = 0; mt < 2; ++mt)
    #pragma unroll
    for (int nt = 0; nt < 8; ++nt)
      #pragma unroll
      for (int q = 0; q < 4; ++q) acc[mt][nt][q] = 0.0f;

  issue(0, 0);

  for (int c = 0; c < NCH; ++c) {
    if (c + 1 < NCH) {
      issue(c + 1, (c + 1) & 1);
      asm volatile("cp.async.wait_group 1;" ::: "memory");
    } else {
      asm volatile("cp.async.wait_group 0;" ::: "memory");
    }
    __syncthreads();

    const uint32_t aBase = sb + (c & 1) * (ABUF + BBUF);
    const uint32_t bBase = aBase + ABUF;

    #pragma unroll
    for (int kb = 0; kb < 2; ++kb) {
      uint32_t afr[2][4];
      #pragma unroll
      for (int mt = 0; mt < 2; ++mt) {
        uint32_t addr = aBase + (wm*32 + mt*16 + (lane & 15)) * 80
                      + kb*32 + (lane >> 4) * 16;
        ldm_x4(afr[mt], addr);
      }
      uint32_t bfr[16];
      #pragma unroll
      for (int nt = 0; nt < 4; ++nt) {
        uint32_t addr = bBase
            + (wn*64 + nt*16 + ((lane >> 4) << 3) + (lane & 7)) * 80
            + kb*32 + ((lane >> 3) & 1) * 16;
        ldm_x4(&bfr[nt * 4], addr);
      }
      #pragma unroll
      for (int mt = 0; mt < 2; ++mt)
        #pragma unroll
        for (int nt = 0; nt < 8; ++nt)
          mma16816(acc[mt][nt], afr[mt], &bfr[nt * 2]);
    }
    __syncthreads();
  }

  // epilogue
  const int r0 = lane >> 2;
  const int c2 = (lane & 3) * 2;
  #pragma unroll
  for (int mt = 0; mt < 2; ++mt) {
    #pragma unroll
    for (int nt = 0; nt < 8; ++nt) {
      const int col = jb + wn*64 + nt*8 + c2;
      if (col < NOUT) {
        const int zr = zb + wm*32 + mt*16 + r0;
        *(float2*)&out[(size_t)zr * NOUT + col] =
            make_float2(acc[mt][nt][0], acc[mt][nt][1]);
        *(float2*)&out[(size_t)(zr + 8) * NOUT + col] =
            make_float2(acc[mt][nt][2], acc[mt][nt][3]);
      }
    }
  }
}

// ---------------------------------------------------------------------------
extern "C" void kernel_launch(void* const* d_in, const int* in_sizes, int n_in,
                              void* d_out, int out_size) {
  const float* r  = (const float*)d_in[0];
  const float* W1 = (const float*)d_in[1];
  const float* b1 = (const float*)d_in[2];
  const float* W2 = (const float*)d_in[3];
  const float* b2 = (const float*)d_in[4];
  const float* cg = (const float*)d_in[5];
  float* out = (float*)d_out;

  const int smem1 = (4096 + 3840 + 64 + 64 + 128*64) * 4;   // 65024 B
  const int smemT = 2 * 64 * 258 * 2;                        // 66048 B
  cudaFuncSetAttribute(feat_kernel,
      cudaFuncAttributeMaxDynamicSharedMemorySize, smem1);
  cudaFuncSetAttribute(transpose_kernel,
      cudaFuncAttributeMaxDynamicSharedMemorySize, smemT);

  feat_kernel<<<ZTOT/128, 128, smem1>>>(r, W1, b1, W2, b2);
  prepB_kernel<<<NBP, 224>>>(cg);
  transpose_kernel<<<ZTOT/64, 256, smemT>>>();
  mma_kernel<<<dim3(3, ZTOT/128), 256>>>(out);
}

// round 8
// speedup vs baseline: 3.4724x; 1.3697x over previous
#include <cuda_runtime.h>
#include <cuda_bf16.h>
#include <math.h>
#include <stdint.h>

#define ZTOT  65536
#define KTOT  204
#define NPATH 60
#define NOUT  324
#define KSEG  224            // per-segment padded K (7 chunks of 32)
#define NCH   21             // 3 segments * 7 chunks
#define NBP   384            // padded B rows

// ---------------- scratch (static device arrays) ----------------
__device__ uint4 g_Fhi4[(size_t)ZTOT * 32];           // [z][256] bf16 hi plane
__device__ uint4 g_Flo4[(size_t)ZTOT * 32];           // [z][256] bf16 lo plane
__device__ __align__(16) __nv_bfloat16 g_B[NBP * 3 * KSEG];  // [n][672] packed segs

// ---------------- helpers ----------------
__device__ __forceinline__ uint32_t smem_u32(const void* p) {
  uint32_t a;
  asm("{ .reg .u64 t; cvta.to.shared.u64 t, %1; cvt.u32.u64 %0, t; }"
      : "=r"(a) : "l"(p));
  return a;
}
__device__ __forceinline__ void cp16(uint32_t smaddr, const void* gptr) {
  asm volatile("cp.async.cg.shared.global [%0], [%1], 16;"
               :: "r"(smaddr), "l"(gptr) : "memory");
}
__device__ __forceinline__ void ldm_x4(uint32_t* r, uint32_t addr) {
  asm volatile("ldmatrix.sync.aligned.m8n8.x4.shared.b16 {%0,%1,%2,%3}, [%4];"
               : "=r"(r[0]), "=r"(r[1]), "=r"(r[2]), "=r"(r[3]) : "r"(addr));
}
__device__ __forceinline__ void mma16816(float* d, const uint32_t* a,
                                         const uint32_t* b) {
  asm volatile(
      "mma.sync.aligned.m16n8k16.row.col.f32.bf16.bf16.f32 "
      "{%0,%1,%2,%3}, {%4,%5,%6,%7}, {%8,%9}, {%0,%1,%2,%3};"
      : "+f"(d[0]), "+f"(d[1]), "+f"(d[2]), "+f"(d[3])
      : "r"(a[0]), "r"(a[1]), "r"(a[2]), "r"(a[3]), "r"(b[0]), "r"(b[1]));
}

// ---------------------------------------------------------------------------
// Kernel 1 (fused): radial MLP + SH -> bf16 hi/lo planes [z][256], no fp32 F.
// Radial basis via factorized exp: B_j = A * t^(m-j) * exp(-4D^2 (m-j)^2),
// two-level recurrence, 3 expf total instead of 64.
// ---------------------------------------------------------------------------
__global__ __launch_bounds__(128) void feat_kernel(
    const float* __restrict__ r,  const float* __restrict__ W1,
    const float* __restrict__ b1, const float* __restrict__ W2,
    const float* __restrict__ b2) {
  extern __shared__ float sm[];
  float* sW1 = sm;                       // 4096
  float* sW2 = sm + 4096;                // 3840
  float* sb1 = sW2 + 3840;               // 64
  float* sb2 = sb1 + 64;                 // 64
  float* sB  = sb2 + 64;                 // union: sB[64][128] / staging (8448 w)
  uint32_t* stg = (uint32_t*)sB;         // staging: 2 planes x [128][33] uint32
  float* sH  = sB + 8448;                // [64][128]
  const int tid = threadIdx.x;

  #pragma unroll
  for (int i = 0; i < 32; ++i) sW1[tid + i*128] = W1[tid + i*128];
  #pragma unroll
  for (int i = 0; i < 30; ++i) sW2[tid + i*128] = W2[tid + i*128];
  if (tid < 64) sb1[tid] = b1[tid];
  if (tid < 60) sb2[tid] = b2[tid];
  __syncthreads();

  const int zb = blockIdx.x * 128;
  const int z = zb + tid;
  const float rx = r[3*z+0], ry = r[3*z+1], rz = r[3*z+2];
  const float rad = sqrtf(rx*rx + ry*ry + rz*rz);
  const float inv = 1.0f / (rad + 1e-12f);
  const float x = rx*inv, y = ry*inv, zc = rz*inv;

  float Y[9];
  Y[0] = 0.28209479177387814f;
  Y[1] = 0.4886025119029199f * y;
  Y[2] = 0.4886025119029199f * zc;
  Y[3] = 0.4886025119029199f * x;
  Y[4] = 1.0925484305920792f * x * y;
  Y[5] = 1.0925484305920792f * y * zc;
  Y[6] = 0.31539156525252005f * (3.0f*zc*zc - 1.0f);
  Y[7] = 1.0925484305920792f * x * zc;
  Y[8] = 0.5462742152960396f * (x*x - y*y);

  // ---- radial basis into sB[j][tid], factorized ----
  {
    const float DLT = 3.5f / 63.0f;
    int m = (int)floorf(rad / DLT + 0.5f);
    m = (m < 0) ? 0 : ((m > 63) ? 63 : m);
    const float u = rad - DLT * (float)m;
    const float A   = expf(-4.0f * u * u);
    const float tdn = expf(-0.44444444f * u);   // exp(-8*DLT*u)
    const float tup = expf( 0.44444444f * u);
    const float G1 = 0.98773021f;               // exp(-4*DLT^2)
    const float W  = 0.97561098f;               // exp(-8*DLT^2)
    sB[m*128 + tid] = A;
    float P = A, q = tdn * G1;
    for (int j = m - 1; j >= 0; --j) { P *= q; q *= W; sB[j*128 + tid] = P; }
    P = A; q = tup * G1;
    for (int j = m + 1; j < 64; ++j) { P *= q; q *= W; sB[j*128 + tid] = P; }
  }
  __syncthreads();

  // hidden = relu(B @ W1 + b1) -> sH
  for (int h = 0; h < 64; ++h) {
    float a = sb1[h];
    #pragma unroll
    for (int j = 0; j < 64; ++j) a = fmaf(sB[j*128 + tid], sW1[j*64 + h], a);
    sH[h*128 + tid] = fmaxf(a, 0.0f);
  }
  __syncthreads();   // sB region will be reused as staging

  float R[NPATH];
  #pragma unroll
  for (int p = 0; p < NPATH; ++p) R[p] = sb2[p];
  for (int h = 0; h < 64; ++h) {
    float hv = sH[h*128 + tid];
    #pragma unroll
    for (int p = 0; p < NPATH; ++p) R[p] = fmaf(hv, sW2[h*60 + p], R[p]);
  }

  // ---- emit bf16 hi/lo planes in 4 chunks of 64 k ----
  constexpr int LF[15]   = {0,1,2,1,0,1,2,1,2,2,1,2,0,1,2};
  constexpr int GOFF[15] = {0,4,16,36,48,52,64,84,96,116,136,148,168,172,184};
  __nv_bfloat16* stHi = (__nv_bfloat16*)stg;              // [128][66]
  __nv_bfloat16* stLo = (__nv_bfloat16*)(stg + 128*33);

  #pragma unroll
  for (int c = 0; c < 4; ++c) {
    __syncthreads();   // previous flush done
    if (c == 3) {      // zero pad k >= 204 (words 6..31 of chunk 3)
      #pragma unroll
      for (int w = 6; w < 32; ++w) {
        stg[tid*33 + w] = 0u;
        stg[128*33 + tid*33 + w] = 0u;
      }
    }
    #pragma unroll
    for (int p = 0; p < NPATH; ++p) {
      const int l  = LF[p >> 2];
      const int yo = (l == 0) ? 0 : ((l == 1) ? 1 : 4);
      const int kb = GOFF[p >> 2] + (p & 3) * (2*l + 1);
      #pragma unroll
      for (int mm = 0; mm < 2*l + 1; ++mm) {
        const int k = kb + mm;
        if (k >= c*64 && k < c*64 + 64) {
          const int kk = k - c*64;
          float f = R[p] * Y[yo + mm];
          __nv_bfloat16 hi = __float2bfloat16(f);
          __nv_bfloat16 lo = __float2bfloat16(f - __bfloat162float(hi));
          stHi[tid*66 + kk] = hi;
          stLo[tid*66 + kk] = lo;
        }
      }
    }
    __syncthreads();
    #pragma unroll
    for (int it = 0; it < 16; ++it) {
      int i = tid + it * 128;              // 0..2047
      int plane = i >> 10;
      int j = i & 1023;
      int row = j >> 3, q = j & 7;
      const uint32_t* src = stg + plane*(128*33) + row*33 + q*4;
      uint4 v; v.x = src[0]; v.y = src[1]; v.z = src[2]; v.w = src[3];
      (plane ? g_Flo4 : g_Fhi4)[(size_t)(zb + row) * 32 + c*8 + q] = v;
    }
  }
}

// ---------------------------------------------------------------------------
// Kernel 2: pack B = cg^T with segments {hi, lo, hi} along K' (672)
// ---------------------------------------------------------------------------
__global__ void prepB_kernel(const float* __restrict__ cg) {
  const int n = blockIdx.x;               // 0..383
  for (int kp = threadIdx.x; kp < 3 * KSEG; kp += blockDim.x) {
    const int seg = kp / KSEG;
    const int k = kp - seg * KSEG;
    float v = (n < NOUT && k < KTOT) ? cg[k * NOUT + n] : 0.0f;
    __nv_bfloat16 hi = __float2bfloat16(v);
    __nv_bfloat16 lo = __float2bfloat16(v - __bfloat162float(hi));
    g_B[n * (3 * KSEG) + kp] = (seg == 1) ? lo : hi;
  }
}

// ---------------------------------------------------------------------------
// Kernel 3: mma.sync bf16 GEMM  out[128z x 128c] per CTA, K'=672
// 3-stage cp.async pipeline, one __syncthreads per k32 chunk.
// ---------------------------------------------------------------------------
#define ABUF 10240
#define BBUF 10240
#define STGN 3
__global__ __launch_bounds__(256) void mma_kernel(float* __restrict__ out) {
  extern __shared__ char smem[];
  const uint32_t sb = smem_u32(smem);
  const int tid = threadIdx.x;
  const int w = tid >> 5, lane = tid & 31;
  const int wm = w >> 1, wn = w & 1;           // 4 x 2 warp grid
  const int jb = blockIdx.x * 128;
  const int zb = blockIdx.y * 128;

  auto issue = [&](int c, int buf) {
    const int seg = (c >= 14) ? 2 : (c >= 7 ? 1 : 0);
    const int wc  = c - seg * 7;
    const uint4* Asrc = (seg == 2) ? g_Flo4 : g_Fhi4;
    const uint4* Bsrc = (const uint4*)g_B;
    const uint32_t base = sb + buf * (ABUF + BBUF);
    #pragma unroll
    for (int it = 0; it < 2; ++it) {
      int i = tid + it * 256;                  // 0..511
      int row = i >> 2, quad = i & 3;
      cp16(base + row * 80 + quad * 16,
           &Asrc[(size_t)(zb + row) * 32 + wc * 4 + quad]);
      cp16(base + ABUF + row * 80 + quad * 16,
           &Bsrc[(size_t)(jb + row) * 84 + c * 4 + quad]);
    }
    asm volatile("cp.async.commit_group;" ::: "memory");
  };

  float acc[2][8][4];
  #pragma unroll
  for (int mt = 0; mt < 2; ++mt)
    #pragma unroll
    for (int nt = 0; nt < 8; ++nt)
      #pragma unroll
      for (int q = 0; q < 4; ++q) acc[mt][nt][q] = 0.0f;

  issue(0, 0);
  issue(1, 1);

  for (int c = 0; c < NCH; ++c) {
    if (c >= NCH - 2)
      asm volatile("cp.async.wait_group 0;" ::: "memory");
    else
      asm volatile("cp.async.wait_group 1;" ::: "memory");
    __syncthreads();

    if (c + 2 < NCH) issue(c + 2, (c + 2) % STGN);

    const uint32_t aBase = sb + (c % STGN) * (ABUF + BBUF);
    const uint32_t bBase = aBase + ABUF;

    #pragma unroll
    for (int kb = 0; kb < 2; ++kb) {
      uint32_t afr[2][4];
      #pragma unroll
      for (int mt = 0; mt < 2; ++mt) {
        uint32_t addr = aBase + (wm*32 + mt*16 + (lane & 15)) * 80
                      + kb*32 + (lane >> 4) * 16;
        ldm_x4(afr[mt], addr);
      }
      uint32_t bfr[16];
      #pragma unroll
      for (int nt = 0; nt < 4; ++nt) {
        uint32_t addr = bBase
            + (wn*64 + nt*16 + ((lane >> 4) << 3) + (lane & 7)) * 80
            + kb*32 + ((lane >> 3) & 1) * 16;
        ldm_x4(&bfr[nt * 4], addr);
      }
      #pragma unroll
      for (int mt = 0; mt < 2; ++mt)
        #pragma unroll
        for (int nt = 0; nt < 8; ++nt)
          mma16816(acc[mt][nt], afr[mt], &bfr[nt * 2]);
    }
  }

  // epilogue
  const int r0 = lane >> 2;
  const int c2 = (lane & 3) * 2;
  #pragma unroll
  for (int mt = 0; mt < 2; ++mt) {
    #pragma unroll
    for (int nt = 0; nt < 8; ++nt) {
      const int col = jb + wn*64 + nt*8 + c2;
      if (col < NOUT) {
        const int zr = zb + wm*32 + mt*16 + r0;
        *(float2*)&out[(size_t)zr * NOUT + col] =
            make_float2(acc[mt][nt][0], acc[mt][nt][1]);
        *(float2*)&out[(size_t)(zr + 8) * NOUT + col] =
            make_float2(acc[mt][nt][2], acc[mt][nt][3]);
      }
    }
  }
}

// ---------------------------------------------------------------------------
extern "C" void kernel_launch(void* const* d_in, const int* in_sizes, int n_in,
                              void* d_out, int out_size) {
  const float* r  = (const float*)d_in[0];
  const float* W1 = (const float*)d_in[1];
  const float* b1 = (const float*)d_in[2];
  const float* W2 = (const float*)d_in[3];
  const float* b2 = (const float*)d_in[4];
  const float* cg = (const float*)d_in[5];
  float* out = (float*)d_out;

  // feat smem: 8064 weights + 8448 union + 8192 sH floats = 98816 B
  const int smem1 = (8064 + 8448 + 8192) * 4;
  const int smem3 = STGN * (ABUF + BBUF);               // 61440 B
  cudaFuncSetAttribute(feat_kernel,
      cudaFuncAttributeMaxDynamicSharedMemorySize, smem1);
  cudaFuncSetAttribute(mma_kernel,
      cudaFuncAttributeMaxDynamicSharedMemorySize, smem3);

  feat_kernel<<<ZTOT/128, 128, smem1>>>(r, W1, b1, W2, b2);
  prepB_kernel<<<NBP, 224>>>(cg);
  mma_kernel<<<dim3(3, ZTOT/128), 256, smem3>>>(out);
}

// round 9
// speedup vs baseline: 3.6604x; 1.0541x over previous
#include <cuda_runtime.h>
#include <cuda_bf16.h>
#include <math.h>
#include <stdint.h>

#define ZTOT  65536
#define KTOT  204
#define NPATH 60
#define NOUT  324
#define KSEG  224            // per-segment padded K
#define NCH2  11             // k64 chunks over K'=672 (last is half)
#define NBP   384            // padded B rows

// ---------------- scratch (static device arrays) ----------------
__device__ uint4 g_Fhi4[(size_t)ZTOT * 32];           // [z][256] bf16 hi plane
__device__ uint4 g_Flo4[(size_t)ZTOT * 32];           // [z][256] bf16 lo plane
__device__ __align__(16) __nv_bfloat16 g_B[NBP * 3 * KSEG];  // [n][672]

// ---------------- helpers ----------------
__device__ __forceinline__ uint32_t smem_u32(const void* p) {
  uint32_t a;
  asm("{ .reg .u64 t; cvta.to.shared.u64 t, %1; cvt.u32.u64 %0, t; }"
      : "=r"(a) : "l"(p));
  return a;
}
__device__ __forceinline__ void cp16(uint32_t smaddr, const void* gptr) {
  asm volatile("cp.async.cg.shared.global [%0], [%1], 16;"
               :: "r"(smaddr), "l"(gptr) : "memory");
}
__device__ __forceinline__ void ldm_x4(uint32_t* r, uint32_t addr) {
  asm volatile("ldmatrix.sync.aligned.m8n8.x4.shared.b16 {%0,%1,%2,%3}, [%4];"
               : "=r"(r[0]), "=r"(r[1]), "=r"(r[2]), "=r"(r[3]) : "r"(addr));
}
__device__ __forceinline__ void mma16816(float* d, const uint32_t* a,
                                         const uint32_t* b) {
  asm volatile(
      "mma.sync.aligned.m16n8k16.row.col.f32.bf16.bf16.f32 "
      "{%0,%1,%2,%3}, {%4,%5,%6,%7}, {%8,%9}, {%0,%1,%2,%3};"
      : "+f"(d[0]), "+f"(d[1]), "+f"(d[2]), "+f"(d[3])
      : "r"(a[0]), "r"(a[1]), "r"(a[2]), "r"(a[3]), "r"(b[0]), "r"(b[1]));
}

// ---------------------------------------------------------------------------
// Kernel 1 (fused): radial MLP + SH -> bf16 hi/lo planes [z][256].
// Basis in registers; W1 transposed in smem; H never materialized.
// ---------------------------------------------------------------------------
__global__ __launch_bounds__(128, 3) void feat_kernel(
    const float* __restrict__ r,  const float* __restrict__ W1,
    const float* __restrict__ b1, const float* __restrict__ W2,
    const float* __restrict__ b2) {
  extern __shared__ float sm[];
  float* sW1t = sm;                      // [64][68] transposed, 4352
  float* sW2  = sm + 4352;               // [64][60], 3840
  float* sb1  = sm + 8192;               // 64
  float* sb2  = sm + 8256;               // 64
  float* sB   = sm + 8320;               // union: basis [64][128] / staging 8448
  uint32_t* stg = (uint32_t*)sB;         // staging: 2 planes x [128][33] uint32
  const int tid = threadIdx.x;

  #pragma unroll
  for (int i = 0; i < 32; ++i) {
    int idx = tid + i * 128;
    int j = idx >> 6, h = idx & 63;      // W1[j][h]
    sW1t[h * 68 + j] = W1[idx];
  }
  #pragma unroll
  for (int i = 0; i < 30; ++i) sW2[tid + i*128] = W2[tid + i*128];
  if (tid < 64) sb1[tid] = b1[tid];
  if (tid < 60) sb2[tid] = b2[tid];
  __syncthreads();

  const int zb = blockIdx.x * 128;
  const int z = zb + tid;
  const float rx = r[3*z+0], ry = r[3*z+1], rz = r[3*z+2];
  const float rad = sqrtf(rx*rx + ry*ry + rz*rz);
  const float inv = 1.0f / (rad + 1e-12f);
  const float x = rx*inv, y = ry*inv, zc = rz*inv;

  float Y[9];
  Y[0] = 0.28209479177387814f;
  Y[1] = 0.4886025119029199f * y;
  Y[2] = 0.4886025119029199f * zc;
  Y[3] = 0.4886025119029199f * x;
  Y[4] = 1.0925484305920792f * x * y;
  Y[5] = 1.0925484305920792f * y * zc;
  Y[6] = 0.31539156525252005f * (3.0f*zc*zc - 1.0f);
  Y[7] = 1.0925484305920792f * x * zc;
  Y[8] = 0.5462742152960396f * (x*x - y*y);

  // ---- radial basis into sB[j][tid] (dynamic recurrence), 3 expf ----
  {
    const float DLT = 3.5f / 63.0f;
    int m = (int)floorf(rad / DLT + 0.5f);
    m = (m < 0) ? 0 : ((m > 63) ? 63 : m);
    const float u = rad - DLT * (float)m;
    const float A   = expf(-4.0f * u * u);
    const float tdn = expf(-0.44444444f * u);
    const float tup = expf( 0.44444444f * u);
    const float G1 = 0.98773021f;
    const float W  = 0.97561098f;
    sB[m*128 + tid] = A;
    float P = A, q = tdn * G1;
    for (int j = m - 1; j >= 0; --j) { P *= q; q *= W; sB[j*128 + tid] = P; }
    P = A; q = tup * G1;
    for (int j = m + 1; j < 64; ++j) { P *= q; q *= W; sB[j*128 + tid] = P; }
  }
  __syncthreads();

  // basis -> registers (static indexing)
  float Bv[64];
  #pragma unroll
  for (int j = 0; j < 64; ++j) Bv[j] = sB[j*128 + tid];

  // fused hidden + R accumulation (no sH)
  float R[NPATH];
  #pragma unroll
  for (int p = 0; p < NPATH; ++p) R[p] = sb2[p];
  #pragma unroll 4
  for (int h = 0; h < 64; ++h) {
    float a = sb1[h];
    #pragma unroll
    for (int j4 = 0; j4 < 16; ++j4) {
      float4 w = *(const float4*)&sW1t[h*68 + j4*4];
      a = fmaf(Bv[4*j4+0], w.x, a);
      a = fmaf(Bv[4*j4+1], w.y, a);
      a = fmaf(Bv[4*j4+2], w.z, a);
      a = fmaf(Bv[4*j4+3], w.w, a);
    }
    a = fmaxf(a, 0.0f);
    #pragma unroll
    for (int p4 = 0; p4 < 15; ++p4) {
      float4 w = *(const float4*)&sW2[h*60 + p4*4];
      R[4*p4+0] = fmaf(a, w.x, R[4*p4+0]);
      R[4*p4+1] = fmaf(a, w.y, R[4*p4+1]);
      R[4*p4+2] = fmaf(a, w.z, R[4*p4+2]);
      R[4*p4+3] = fmaf(a, w.w, R[4*p4+3]);
    }
  }

  // ---- emit bf16 hi/lo planes in 4 chunks of 64 k ----
  constexpr int LF[15]   = {0,1,2,1,0,1,2,1,2,2,1,2,0,1,2};
  constexpr int GOFF[15] = {0,4,16,36,48,52,64,84,96,116,136,148,168,172,184};
  __nv_bfloat16* stHi = (__nv_bfloat16*)stg;              // [128][66]
  __nv_bfloat16* stLo = (__nv_bfloat16*)(stg + 128*33);

  #pragma unroll
  for (int c = 0; c < 4; ++c) {
    __syncthreads();
    if (c == 3) {
      #pragma unroll
      for (int w = 6; w < 32; ++w) {
        stg[tid*33 + w] = 0u;
        stg[128*33 + tid*33 + w] = 0u;
      }
    }
    #pragma unroll
    for (int p = 0; p < NPATH; ++p) {
      const int l  = LF[p >> 2];
      const int yo = (l == 0) ? 0 : ((l == 1) ? 1 : 4);
      const int kb = GOFF[p >> 2] + (p & 3) * (2*l + 1);
      #pragma unroll
      for (int mm = 0; mm < 2*l + 1; ++mm) {
        const int k = kb + mm;
        if (k >= c*64 && k < c*64 + 64) {
          const int kk = k - c*64;
          float f = R[p] * Y[yo + mm];
          __nv_bfloat16 hi = __float2bfloat16(f);
          __nv_bfloat16 lo = __float2bfloat16(f - __bfloat162float(hi));
          stHi[tid*66 + kk] = hi;
          stLo[tid*66 + kk] = lo;
        }
      }
    }
    __syncthreads();
    #pragma unroll
    for (int it = 0; it < 16; ++it) {
      int i = tid + it * 128;
      int plane = i >> 10;
      int j = i & 1023;
      int row = j >> 3, q = j & 7;
      const uint32_t* src = stg + plane*(128*33) + row*33 + q*4;
      uint4 v; v.x = src[0]; v.y = src[1]; v.z = src[2]; v.w = src[3];
      (plane ? g_Flo4 : g_Fhi4)[(size_t)(zb + row) * 32 + c*8 + q] = v;
    }
  }
}

// ---------------------------------------------------------------------------
// Kernel 2: pack B = cg^T with segments {hi, lo, hi} along K' (672)
// ---------------------------------------------------------------------------
__global__ void prepB_kernel(const float* __restrict__ cg) {
  const int n = blockIdx.x;
  for (int kp = threadIdx.x; kp < 3 * KSEG; kp += blockDim.x) {
    const int seg = kp / KSEG;
    const int k = kp - seg * KSEG;
    float v = (n < NOUT && k < KTOT) ? cg[k * NOUT + n] : 0.0f;
    __nv_bfloat16 hi = __float2bfloat16(v);
    __nv_bfloat16 lo = __float2bfloat16(v - __bfloat162float(hi));
    g_B[n * (3 * KSEG) + kp] = (seg == 1) ? lo : hi;
  }
}

// ---------------------------------------------------------------------------
// Kernel 3: mma.sync bf16 GEMM, K'=672, k64 pipeline stages (144B rows),
// 3-stage cp.async ring, tail chunk (32 k) peeled.
// ---------------------------------------------------------------------------
#define ABUF 18432
#define BBUF 18432
#define STGN 3
__global__ __launch_bounds__(256) void mma_kernel(float* __restrict__ out) {
  extern __shared__ char smem[];
  const uint32_t sb = smem_u32(smem);
  const int tid = threadIdx.x;
  const int w = tid >> 5, lane = tid & 31;
  const int wm = w >> 1, wn = w & 1;           // 4 x 2 warp grid
  const int jb = blockIdx.x * 128;
  const int zb = blockIdx.y * 128;

  auto issue = [&](int c, int buf) {
    const uint32_t base = sb + buf * (ABUF + BBUF);
    const char* Bb = (const char*)g_B;
    #pragma unroll
    for (int it = 0; it < 4; ++it) {
      int i = tid + it * 256;                  // 0..1023
      int row = i >> 3, quad = i & 7;
      int kp = c * 64 + quad * 8;
      if (kp < 672) {
        int seg = (kp >= 448) ? 2 : (kp >= 224 ? 1 : 0);
        int kk = kp - seg * 224;
        const char* Asrc = (const char*)(seg == 2 ? g_Flo4 : g_Fhi4)
                           + (size_t)(zb + row) * 512 + kk * 2;
        cp16(base + row * 144 + quad * 16, Asrc);
        cp16(base + ABUF + row * 144 + quad * 16,
             Bb + (size_t)(jb + row) * 1344 + kp * 2);
      }
    }
    asm volatile("cp.async.commit_group;" ::: "memory");
  };

  float acc[2][8][4];
  #pragma unroll
  for (int mt = 0; mt < 2; ++mt)
    #pragma unroll
    for (int nt = 0; nt < 8; ++nt)
      #pragma unroll
      for (int q = 0; q < 4; ++q) acc[mt][nt][q] = 0.0f;

  issue(0, 0);
  issue(1, 1);

  for (int c = 0; c < NCH2; ++c) {
    if (c >= NCH2 - 1)
      asm volatile("cp.async.wait_group 0;" ::: "memory");
    else
      asm volatile("cp.async.wait_group 1;" ::: "memory");
    __syncthreads();

    if (c + 2 < NCH2) issue(c + 2, (c + 2) % STGN);

    const uint32_t aBase = sb + (c % STGN) * (ABUF + BBUF);
    const uint32_t bBase = aBase + ABUF;

    auto step = [&](int kb) {
      uint32_t afr[2][4];
      #pragma unroll
      for (int mt = 0; mt < 2; ++mt) {
        uint32_t addr = aBase + (wm*32 + mt*16 + (lane & 15)) * 144
                      + kb*32 + (lane >> 4) * 16;
        ldm_x4(afr[mt], addr);
      }
      uint32_t bfr[16];
      #pragma unroll
      for (int nt = 0; nt < 4; ++nt) {
        uint32_t addr = bBase
            + (wn*64 + nt*16 + ((lane >> 4) << 3) + (lane & 7)) * 144
            + kb*32 + ((lane >> 3) & 1) * 16;
        ldm_x4(&bfr[nt * 4], addr);
      }
      #pragma unroll
      for (int mt = 0; mt < 2; ++mt)
        #pragma unroll
        for (int nt = 0; nt < 8; ++nt)
          mma16816(acc[mt][nt], afr[mt], &bfr[nt * 2]);
    };

    if (c < NCH2 - 1) {
      #pragma unroll
      for (int kb = 0; kb < 4; ++kb) step(kb);
    } else {           // tail chunk: only 32 valid k
      step(0);
      step(1);
    }
  }

  // epilogue
  const int r0 = lane >> 2;
  const int c2 = (lane & 3) * 2;
  #pragma unroll
  for (int mt = 0; mt < 2; ++mt) {
    #pragma unroll
    for (int nt = 0; nt < 8; ++nt) {
      const int col = jb + wn*64 + nt*8 + c2;
      if (col < NOUT) {
        const int zr = zb + wm*32 + mt*16 + r0;
        *(float2*)&out[(size_t)zr * NOUT + col] =
            make_float2(acc[mt][nt][0], acc[mt][nt][1]);
        *(float2*)&out[(size_t)(zr + 8) * NOUT + col] =
            make_float2(acc[mt][nt][2], acc[mt][nt][3]);
      }
    }
  }
}

// ---------------------------------------------------------------------------
extern "C" void kernel_launch(void* const* d_in, const int* in_sizes, int n_in,
                              void* d_out, int out_size) {
  const float* r  = (const float*)d_in[0];
  const float* W1 = (const float*)d_in[1];
  const float* b1 = (const float*)d_in[2];
  const float* W2 = (const float*)d_in[3];
  const float* b2 = (const float*)d_in[4];
  const float* cg = (const float*)d_in[5];
  float* out = (float*)d_out;

  const int smem1 = (4352 + 3840 + 128 + 8448) * 4;     // 67072 B
  const int smem3 = STGN * (ABUF + BBUF);               // 110592 B
  cudaFuncSetAttribute(feat_kernel,
      cudaFuncAttributeMaxDynamicSharedMemorySize, smem1);
  cudaFuncSetAttribute(mma_kernel,
      cudaFuncAttributeMaxDynamicSharedMemorySize, smem3);

  feat_kernel<<<ZTOT/128, 128, smem1>>>(r, W1, b1, W2, b2);
  prepB_kernel<<<NBP, 224>>>(cg);
  mma_kernel<<<dim3(3, ZTOT/128), 256, smem3>>>(out);
}

// round 10
// speedup vs baseline: 3.7048x; 1.0122x over previous
#include <cuda_runtime.h>
#include <cuda_bf16.h>
#include <math.h>
#include <stdint.h>

#define ZTOT  65536
#define KTOT  204
#define NPATH 60
#define NOUT  324
#define SEGP  208            // per-segment padding (204 + 4)
#define KP2   624            // K' = 3 * 208
#define CH    48             // k' per chunk
#define NCH   13             // 624 / 48
#define NBP   384

// ---------------- scratch ----------------
__device__ uint4 g_Fhi4[(size_t)ZTOT * 32];           // [z][256] bf16 hi plane
__device__ uint4 g_Flo4[(size_t)ZTOT * 32];           // [z][256] bf16 lo plane
__device__ __align__(16) __nv_bfloat16 g_B[NBP * KP2];

// ---------------- helpers ----------------
__device__ __forceinline__ uint32_t smem_u32(const void* p) {
  uint32_t a;
  asm("{ .reg .u64 t; cvta.to.shared.u64 t, %1; cvt.u32.u64 %0, t; }"
      : "=r"(a) : "l"(p));
  return a;
}
__device__ __forceinline__ void cp16(uint32_t smaddr, const void* gptr) {
  asm volatile("cp.async.cg.shared.global [%0], [%1], 16;"
               :: "r"(smaddr), "l"(gptr) : "memory");
}
__device__ __forceinline__ void ldm_x4(uint32_t* r, uint32_t addr) {
  asm volatile("ldmatrix.sync.aligned.m8n8.x4.shared.b16 {%0,%1,%2,%3}, [%4];"
               : "=r"(r[0]), "=r"(r[1]), "=r"(r[2]), "=r"(r[3]) : "r"(addr));
}
__device__ __forceinline__ void mma16816(float* d, const uint32_t* a,
                                         const uint32_t* b) {
  asm volatile(
      "mma.sync.aligned.m16n8k16.row.col.f32.bf16.bf16.f32 "
      "{%0,%1,%2,%3}, {%4,%5,%6,%7}, {%8,%9}, {%0,%1,%2,%3};"
      : "+f"(d[0]), "+f"(d[1]), "+f"(d[2]), "+f"(d[3])
      : "r"(a[0]), "r"(a[1]), "r"(a[2]), "r"(a[3]), "r"(b[0]), "r"(b[1]));
}

// ---------------------------------------------------------------------------
// Kernel 1 (fused): radial MLP + SH -> bf16 hi/lo planes [z][256].
// 4 independent accumulators in the hidden dot product.
// ---------------------------------------------------------------------------
__global__ __launch_bounds__(128, 3) void feat_kernel(
    const float* __restrict__ r,  const float* __restrict__ W1,
    const float* __restrict__ b1, const float* __restrict__ W2,
    const float* __restrict__ b2) {
  extern __shared__ float sm[];
  float* sW1t = sm;                      // [64][68] transposed
  float* sW2  = sm + 4352;               // [64][60]
  float* sb1  = sm + 8192;
  float* sb2  = sm + 8256;
  float* sB   = sm + 8320;               // union: basis [64][128] / staging
  uint32_t* stg = (uint32_t*)sB;         // 2 planes x [128][33] uint32
  const int tid = threadIdx.x;

  #pragma unroll
  for (int i = 0; i < 32; ++i) {
    int idx = tid + i * 128;
    int j = idx >> 6, h = idx & 63;
    sW1t[h * 68 + j] = W1[idx];
  }
  #pragma unroll
  for (int i = 0; i < 30; ++i) sW2[tid + i*128] = W2[tid + i*128];
  if (tid < 64) sb1[tid] = b1[tid];
  if (tid < 60) sb2[tid] = b2[tid];
  __syncthreads();

  const int zb = blockIdx.x * 128;
  const int z = zb + tid;
  const float rx = r[3*z+0], ry = r[3*z+1], rz = r[3*z+2];
  const float rad = sqrtf(rx*rx + ry*ry + rz*rz);
  const float inv = 1.0f / (rad + 1e-12f);
  const float x = rx*inv, y = ry*inv, zc = rz*inv;

  float Y[9];
  Y[0] = 0.28209479177387814f;
  Y[1] = 0.4886025119029199f * y;
  Y[2] = 0.4886025119029199f * zc;
  Y[3] = 0.4886025119029199f * x;
  Y[4] = 1.0925484305920792f * x * y;
  Y[5] = 1.0925484305920792f * y * zc;
  Y[6] = 0.31539156525252005f * (3.0f*zc*zc - 1.0f);
  Y[7] = 1.0925484305920792f * x * zc;
  Y[8] = 0.5462742152960396f * (x*x - y*y);

  {  // radial basis, factorized (3 expf)
    const float DLT = 3.5f / 63.0f;
    int m = (int)floorf(rad / DLT + 0.5f);
    m = (m < 0) ? 0 : ((m > 63) ? 63 : m);
    const float u = rad - DLT * (float)m;
    const float A   = expf(-4.0f * u * u);
    const float tdn = expf(-0.44444444f * u);
    const float tup = expf( 0.44444444f * u);
    const float G1 = 0.98773021f;
    const float W  = 0.97561098f;
    sB[m*128 + tid] = A;
    float P = A, q = tdn * G1;
    for (int j = m - 1; j >= 0; --j) { P *= q; q *= W; sB[j*128 + tid] = P; }
    P = A; q = tup * G1;
    for (int j = m + 1; j < 64; ++j) { P *= q; q *= W; sB[j*128 + tid] = P; }
  }
  __syncthreads();

  float Bv[64];
  #pragma unroll
  for (int j = 0; j < 64; ++j) Bv[j] = sB[j*128 + tid];

  float R[NPATH];
  #pragma unroll
  for (int p = 0; p < NPATH; ++p) R[p] = sb2[p];
  #pragma unroll 4
  for (int h = 0; h < 64; ++h) {
    float a0 = sb1[h], a1 = 0.f, a2 = 0.f, a3 = 0.f;
    #pragma unroll
    for (int j4 = 0; j4 < 16; ++j4) {
      float4 w = *(const float4*)&sW1t[h*68 + j4*4];
      a0 = fmaf(Bv[4*j4+0], w.x, a0);
      a1 = fmaf(Bv[4*j4+1], w.y, a1);
      a2 = fmaf(Bv[4*j4+2], w.z, a2);
      a3 = fmaf(Bv[4*j4+3], w.w, a3);
    }
    float a = fmaxf((a0 + a1) + (a2 + a3), 0.0f);
    #pragma unroll
    for (int p4 = 0; p4 < 15; ++p4) {
      float4 w = *(const float4*)&sW2[h*60 + p4*4];
      R[4*p4+0] = fmaf(a, w.x, R[4*p4+0]);
      R[4*p4+1] = fmaf(a, w.y, R[4*p4+1]);
      R[4*p4+2] = fmaf(a, w.z, R[4*p4+2]);
      R[4*p4+3] = fmaf(a, w.w, R[4*p4+3]);
    }
  }

  // emit bf16 hi/lo planes in 4 chunks of 64 k
  constexpr int LF[15]   = {0,1,2,1,0,1,2,1,2,2,1,2,0,1,2};
  constexpr int GOFF[15] = {0,4,16,36,48,52,64,84,96,116,136,148,168,172,184};
  __nv_bfloat16* stHi = (__nv_bfloat16*)stg;              // [128][66]
  __nv_bfloat16* stLo = (__nv_bfloat16*)(stg + 128*33);

  #pragma unroll
  for (int c = 0; c < 4; ++c) {
    __syncthreads();
    if (c == 3) {
      #pragma unroll
      for (int w = 6; w < 32; ++w) {
        stg[tid*33 + w] = 0u;
        stg[128*33 + tid*33 + w] = 0u;
      }
    }
    #pragma unroll
    for (int p = 0; p < NPATH; ++p) {
      const int l  = LF[p >> 2];
      const int yo = (l == 0) ? 0 : ((l == 1) ? 1 : 4);
      const int kb = GOFF[p >> 2] + (p & 3) * (2*l + 1);
      #pragma unroll
      for (int mm = 0; mm < 2*l + 1; ++mm) {
        const int k = kb + mm;
        if (k >= c*64 && k < c*64 + 64) {
          const int kk = k - c*64;
          float f = R[p] * Y[yo + mm];
          __nv_bfloat16 hi = __float2bfloat16(f);
          __nv_bfloat16 lo = __float2bfloat16(f - __bfloat162float(hi));
          stHi[tid*66 + kk] = hi;
          stLo[tid*66 + kk] = lo;
        }
      }
    }
    __syncthreads();
    #pragma unroll
    for (int it = 0; it < 16; ++it) {
      int i = tid + it * 128;
      int plane = i >> 10;
      int j = i & 1023;
      int row = j >> 3, q = j & 7;
      const uint32_t* src = stg + plane*(128*33) + row*33 + q*4;
      uint4 v; v.x = src[0]; v.y = src[1]; v.z = src[2]; v.w = src[3];
      (plane ? g_Flo4 : g_Fhi4)[(size_t)(zb + row) * 32 + c*8 + q] = v;
    }
  }
}

// ---------------------------------------------------------------------------
// Kernel 2: pack B = cg^T, segments {hi, lo, hi} at offsets 0/208/416
// ---------------------------------------------------------------------------
__global__ void prepB_kernel(const float* __restrict__ cg) {
  const int n = blockIdx.x;
  for (int kp = threadIdx.x; kp < KP2; kp += blockDim.x) {
    const int seg = kp / SEGP;
    const int k = kp - seg * SEGP;
    float v = (n < NOUT && k < KTOT) ? cg[k * NOUT + n] : 0.0f;
    __nv_bfloat16 hi = __float2bfloat16(v);
    __nv_bfloat16 lo = __float2bfloat16(v - __bfloat162float(hi));
    g_B[n * KP2 + kp] = (seg == 1) ? lo : hi;
  }
}

// ---------------------------------------------------------------------------
// Kernel 3: mma.sync bf16 GEMM, K'=624, 13 chunks of k48, 512 threads,
// 4x4 warp grid (warp tile 32x32), 3-stage cp.async ring, 112B rows.
// ---------------------------------------------------------------------------
#define ABUF 14336           // 128 * 112
#define BBUF 14336
#define STGN 3
__global__ __launch_bounds__(512) void mma_kernel(float* __restrict__ out) {
  extern __shared__ char smem[];
  const uint32_t sb = smem_u32(smem);
  const int tid = threadIdx.x;
  const int w = tid >> 5, lane = tid & 31;
  const int wm = w >> 2, wn = w & 3;           // 4 x 4 warp grid
  const int jb = blockIdx.x * 128;
  const int zb = blockIdx.y * 128;

  auto issue = [&](int c, int buf) {
    const uint32_t base = sb + buf * (ABUF + BBUF);
    const char* Bb = (const char*)g_B;
    #pragma unroll
    for (int it = 0; it < 3; ++it) {
      int i = tid + it * 512;                  // 0..1535
      int half = i >= 768;                     // 0: A, 1: B
      int j = i - half * 768;
      int row = j / 6, quad = j - row * 6;
      int kp = c * CH + quad * 8;
      uint32_t dst = base + half * ABUF + row * 112 + quad * 16;
      if (half) {
        cp16(dst, Bb + (size_t)(jb + row) * (KP2*2) + kp * 2);
      } else {
        int seg = (kp >= 2*SEGP) ? 2 : (kp >= SEGP ? 1 : 0);
        int kk = kp - seg * SEGP;
        const char* Asrc = (const char*)(seg == 2 ? g_Flo4 : g_Fhi4)
                           + (size_t)(zb + row) * 512 + kk * 2;
        cp16(dst, Asrc);
      }
    }
    asm volatile("cp.async.commit_group;" ::: "memory");
  };

  float acc[2][4][4];
  #pragma unroll
  for (int mt = 0; mt < 2; ++mt)
    #pragma unroll
    for (int nt = 0; nt < 4; ++nt)
      #pragma unroll
      for (int q = 0; q < 4; ++q) acc[mt][nt][q] = 0.0f;

  issue(0, 0);
  issue(1, 1);

  for (int c = 0; c < NCH; ++c) {
    if (c >= NCH - 2)
      asm volatile("cp.async.wait_group 0;" ::: "memory");
    else
      asm volatile("cp.async.wait_group 1;" ::: "memory");
    __syncthreads();

    if (c + 2 < NCH) issue(c + 2, (c + 2) % STGN);

    const uint32_t aBase = sb + (c % STGN) * (ABUF + BBUF);
    const uint32_t bBase = aBase + ABUF;

    #pragma unroll
    for (int ks = 0; ks < 3; ++ks) {
      uint32_t afr[2][4];
      #pragma unroll
      for (int mt = 0; mt < 2; ++mt) {
        uint32_t addr = aBase + (wm*32 + mt*16 + (lane & 15)) * 112
                      + ks*32 + (lane >> 4) * 16;
        ldm_x4(afr[mt], addr);
      }
      uint32_t bfr[8];
      #pragma unroll
      for (int nt = 0; nt < 2; ++nt) {
        uint32_t addr = bBase
            + (wn*32 + nt*16 + ((lane >> 4) << 3) + (lane & 7)) * 112
            + ks*32 + ((lane >> 3) & 1) * 16;
        ldm_x4(&bfr[nt * 4], addr);
      }
      #pragma unroll
      for (int mt = 0; mt < 2; ++mt)
        #pragma unroll
        for (int nt = 0; nt < 4; ++nt)
          mma16816(acc[mt][nt], afr[mt], &bfr[nt * 2]);
    }
  }

  // epilogue
  const int r0 = lane >> 2;
  const int c2 = (lane & 3) * 2;
  #pragma unroll
  for (int mt = 0; mt < 2; ++mt) {
    #pragma unroll
    for (int nt = 0; nt < 4; ++nt) {
      const int col = jb + wn*32 + nt*8 + c2;
      if (col < NOUT) {
        const int zr = zb + wm*32 + mt*16 + r0;
        *(float2*)&out[(size_t)zr * NOUT + col] =
            make_float2(acc[mt][nt][0], acc[mt][nt][1]);
        *(float2*)&out[(size_t)(zr + 8) * NOUT + col] =
            make_float2(acc[mt][nt][2], acc[mt][nt][3]);
      }
    }
  }
}

// ---------------------------------------------------------------------------
extern "C" void kernel_launch(void* const* d_in, const int* in_sizes, int n_in,
                              void* d_out, int out_size) {
  const float* r  = (const float*)d_in[0];
  const float* W1 = (const float*)d_in[1];
  const float* b1 = (const float*)d_in[2];
  const float* W2 = (const float*)d_in[3];
  const float* b2 = (const float*)d_in[4];
  const float* cg = (const float*)d_in[5];
  float* out = (float*)d_out;

  const int smem1 = (4352 + 3840 + 128 + 8448) * 4;     // 67072 B
  const int smem3 = STGN * (ABUF + BBUF);               // 86016 B
  cudaFuncSetAttribute(feat_kernel,
      cudaFuncAttributeMaxDynamicSharedMemorySize, smem1);
  cudaFuncSetAttribute(mma_kernel,
      cudaFuncAttributeMaxDynamicSharedMemorySize, smem3);

  feat_kernel<<<ZTOT/128, 128, smem1>>>(r, W1, b1, W2, b2);
  prepB_kernel<<<NBP, 224>>>(cg);
  mma_kernel<<<dim3(3, ZTOT/128), 512, smem3>>>(out);
}